// round 11
// baseline (speedup 1.0000x reference)
#include <cuda_runtime.h>
#include <cuda_bf16.h>
#include <cstdint>

#define NPTS 1024
#define HDIM 32

typedef unsigned long long u64;
typedef unsigned int u32;

// ---------- scratch ----------
__device__ float g_a[NPTS * HDIM];
__device__ float g_c[(NPTS + 4) * HDIM];          // +4 zero pad rows
__device__ float g_h1[NPTS * HDIM];
__device__ float g_xg[(size_t)NPTS * NPTS * 96];  // [i][j][3 gates][32 lanes] = 384 MiB

// ---------- packed f32x2 helpers ----------
__device__ __forceinline__ u64 f2fma(u64 a, u64 b, u64 c) {
    u64 d;
    asm("fma.rn.f32x2 %0, %1, %2, %3;" : "=l"(d) : "l"(a), "l"(b), "l"(c));
    return d;
}
__device__ __forceinline__ u64 add2(u64 a, u64 b) {
    u64 d;
    asm("add.rn.f32x2 %0, %1, %2;" : "=l"(d) : "l"(a), "l"(b));
    return d;
}
__device__ __forceinline__ u64 pack2(float lo, float hi) {
    u64 r;
    asm("mov.b64 %0, {%1, %2};" : "=l"(r) : "f"(lo), "f"(hi));
    return r;
}
__device__ __forceinline__ float hsum2(u64 v) {
    float lo, hi;
    asm("mov.b64 {%0, %1}, %2;" : "=f"(lo), "=f"(hi) : "l"(v));
    return lo + hi;
}
__device__ __forceinline__ float tanh_hw(float x) {
    float y;
    asm("tanh.approx.f32 %0, %1;" : "=f"(y) : "f"(x));
    return y;
}
__device__ __forceinline__ float sig_hw(float x) {
    return fmaf(tanh_hw(0.5f * x), 0.5f, 0.5f);
}
__device__ __forceinline__ u32 smem_u32(const void* p) {
    u32 a;
    asm("{ .reg .u64 t; cvta.to.shared.u64 t, %1; cvt.u32.u64 %0, t; }"
        : "=r"(a) : "l"(p));
    return a;
}
__device__ __forceinline__ void sts32(u32 addr, float v) {
    asm volatile("st.shared.b32 [%0], %1;" :: "r"(addr), "f"(v) : "memory");
}
__device__ __forceinline__ void lds_v2(u64& p0, u64& p1, u32 addr) {
    asm volatile("ld.shared.v2.u64 {%0, %1}, [%2];"
                 : "=l"(p0), "=l"(p1) : "r"(addr));
}

// ---------- precompute: a_i = (Wa-Wb)@x_i + b ; c_j = Wb@x_j ----------
template <int F>
__global__ void __launch_bounds__(256)
pre_kernel(const float* __restrict__ x, const float* __restrict__ w,
           const float* __restrict__ b, float* __restrict__ a,
           float* __restrict__ c) {
    int wq = threadIdx.x >> 5;
    int l = threadIdx.x & 31;
    int i = blockIdx.x * 8 + wq;
    if (i >= NPTS) return;
    float av = b[l];
    float cv = 0.0f;
    const float* wr = w + l * (2 * F);
    const float* xr = x + i * F;
#pragma unroll
    for (int f = 0; f < F; ++f) {
        float xv = xr[f];
        float wa = wr[f];
        float wb = wr[F + f];
        av = fmaf(wa - wb, xv, av);
        cv = fmaf(wb, xv, cv);
    }
    a[i * HDIM + l] = av;
    c[i * HDIM + l] = cv;
}

// ---------- xg precompute: xg[i,j,:] = Wih @ relu(a_i + c_j) + biases ------
// One warp per (i, j-block of 128). Fully parallel; FMA-bound.
__global__ void __launch_bounds__(128)
xg_kernel(const float* __restrict__ a, const float* __restrict__ c,
          const float* __restrict__ wih, const float* __restrict__ bih,
          const float* __restrict__ bhh, float* __restrict__ xg) {
    __shared__ __align__(16) float s_u[4][2][HDIM];

    const int w = threadIdx.x >> 5;
    const int l = threadIdx.x & 31;
    const int g = blockIdx.x * 4 + w;     // 0..8191
    const int i = g >> 3;
    const int jb = g & 7;                 // 8 blocks of 128 steps

    u64 Wr[16], Wz[16], Wn[16];
    {
        const u64* pr = (const u64*)(wih + (0 * HDIM + l) * HDIM);
        const u64* pz = (const u64*)(wih + (1 * HDIM + l) * HDIM);
        const u64* pn = (const u64*)(wih + (2 * HDIM + l) * HDIM);
#pragma unroll
        for (int q = 0; q < 16; ++q) {
            Wr[q] = pr[q];
            Wz[q] = pz[q];
            Wn[q] = pn[q];
        }
    }
    const float B_r = bih[l] + bhh[l];
    const float B_z = bih[HDIM + l] + bhh[HDIM + l];
    const float B_n = bih[2 * HDIM + l];
    const float a_l = a[i * HDIM + l];

    const u32 ub = smem_u32(&s_u[w][0][0]);

    float cn = c[(jb * 128) * HDIM + l];
    float* xout = xg + ((size_t)i * NPTS + (size_t)jb * 128) * 96 + l;

#pragma unroll 2
    for (int t = 0; t < 128; ++t) {
        const int j = jb * 128 + t;
        const float u = fmaxf(a_l + cn, 0.0f);
        cn = c[(j + 1) * HDIM + l];     // row NPTS is zero pad
        const u32 uo = ub + (u32)(t & 1) * 128u;
        sts32(uo + l * 4u, u);
        __syncwarp();
        u64 r0 = 0ULL, r1 = 0ULL, z0 = 0ULL, z1 = 0ULL, n0 = 0ULL, n1 = 0ULL;
#pragma unroll
        for (int q = 0; q < 8; ++q) {
            u64 p0, p1;
            lds_v2(p0, p1, uo + q * 16u);
            r0 = f2fma(Wr[2 * q], p0, r0);
            r1 = f2fma(Wr[2 * q + 1], p1, r1);
            z0 = f2fma(Wz[2 * q], p0, z0);
            z1 = f2fma(Wz[2 * q + 1], p1, z1);
            n0 = f2fma(Wn[2 * q], p0, n0);
            n1 = f2fma(Wn[2 * q + 1], p1, n1);
        }
        xout[0]  = hsum2(add2(r0, r1)) + B_r;
        xout[32] = hsum2(add2(z0, z1)) + B_z;
        xout[64] = hsum2(add2(n0, n1)) + B_n;
        xout += 96;
    }
}

// ---------- GRU scan: recurrence only (hg matvec + tail), xg streamed ------
template <int FUSE_CLF>
__global__ void __launch_bounds__(128)
gru_scan_kernel(const float* __restrict__ xg, const float* __restrict__ whh,
                const float* __restrict__ bhh,
                const float* __restrict__ clf_w, const float* __restrict__ clf_b,
                float* __restrict__ out) {
    __shared__ __align__(16) float s_h[4][2][HDIM];

    const int w = threadIdx.x >> 5;
    const int l = threadIdx.x & 31;
    const int i = blockIdx.x * 4 + w;

    u64 Whr[16], Whz[16], Whn[16];
    {
        const u64* pr = (const u64*)(whh + (0 * HDIM + l) * HDIM);
        const u64* pz = (const u64*)(whh + (1 * HDIM + l) * HDIM);
        const u64* pn = (const u64*)(whh + (2 * HDIM + l) * HDIM);
#pragma unroll
        for (int q = 0; q < 16; ++q) {
            Whr[q] = pr[q];
            Whz[q] = pz[q];
            Whn[q] = pn[q];
        }
    }
    const u64 init_n = pack2(bhh[2 * HDIM + l], 0.0f);   // b_hn

    const float* xin = xg + (size_t)i * NPTS * 96 + l;
    const u32 hb = smem_u32(&s_h[w][0][0]);

    // prefetch pipeline, distance 4
    float pr_[4], pz_[4], pn_[4];
#pragma unroll
    for (int t = 0; t < 4; ++t) {
        pr_[t] = xin[t * 96];
        pz_[t] = xin[t * 96 + 32];
        pn_[t] = xin[t * 96 + 64];
    }

    float h = 0.0f;

    for (int j = 0; j < NPTS; j += 4) {
#pragma unroll
        for (int s = 0; s < 4; ++s) {
            const int jj = j + s;
            const float xr = pr_[s];
            const float xz = pz_[s];
            const float xn = pn_[s];
            const int jn = (jj + 4 < NPTS) ? (jj + 4) : jj;   // clamp; dup harmless
            pr_[s] = xin[jn * 96];
            pz_[s] = xin[jn * 96 + 32];
            pn_[s] = xin[jn * 96 + 64];

            const u32 ho = hb + (u32)(s & 1) * 128u;
            sts32(ho + l * 4u, h);
            __syncwarp();
            u64 r0 = 0ULL, r1 = 0ULL, z0 = 0ULL, z1 = 0ULL;
            u64 n0 = init_n, n1 = 0ULL;
#pragma unroll
            for (int q = 0; q < 8; ++q) {
                u64 p0, p1;
                lds_v2(p0, p1, ho + q * 16u);
                r0 = f2fma(Whr[2 * q], p0, r0);
                r1 = f2fma(Whr[2 * q + 1], p1, r1);
                z0 = f2fma(Whz[2 * q], p0, z0);
                z1 = f2fma(Whz[2 * q + 1], p1, z1);
                n0 = f2fma(Whn[2 * q], p0, n0);
                n1 = f2fma(Whn[2 * q + 1], p1, n1);
            }
            const float r = sig_hw(xr + hsum2(add2(r0, r1)));
            const float z = sig_hw(xz + hsum2(add2(z0, z1)));
            const float n = tanh_hw(fmaf(r, hsum2(add2(n0, n1)), xn));
            h = fmaf(z, h - n, n);
        }
    }

    if (FUSE_CLF) {
        sts32(hb + l * 4u, h);
        __syncwarp();
        if (l < 3) {
            float acc = clf_b[l];
            const float* cw = clf_w + l * HDIM;
#pragma unroll
            for (int hh = 0; hh < HDIM; ++hh)
                acc = fmaf(cw[hh], s_h[w][0][hh], acc);
            out[i * 3 + l] = acc;
        }
    } else {
        out[i * HDIM + l] = h;
    }
}

extern "C" void kernel_launch(void* const* d_in, const int* in_sizes, int n_in,
                              void* d_out, int out_size) {
    const float* x        = (const float*)d_in[0];
    const float* proj1_w  = (const float*)d_in[1];
    const float* proj1_b  = (const float*)d_in[2];
    const float* gru1_wih = (const float*)d_in[3];
    const float* gru1_whh = (const float*)d_in[4];
    const float* gru1_bih = (const float*)d_in[5];
    const float* gru1_bhh = (const float*)d_in[6];
    const float* proj2_w  = (const float*)d_in[7];
    const float* proj2_b  = (const float*)d_in[8];
    const float* gru2_wih = (const float*)d_in[9];
    const float* gru2_whh = (const float*)d_in[10];
    const float* gru2_bih = (const float*)d_in[11];
    const float* gru2_bhh = (const float*)d_in[12];
    const float* clf_w    = (const float*)d_in[13];
    const float* clf_b    = (const float*)d_in[14];
    float* out = (float*)d_out;

    float *pa, *pc, *ph1, *pxg;
    cudaGetSymbolAddress((void**)&pa, g_a);
    cudaGetSymbolAddress((void**)&pc, g_c);
    cudaGetSymbolAddress((void**)&ph1, g_h1);
    cudaGetSymbolAddress((void**)&pxg, g_xg);

    // Stage 1
    pre_kernel<16><<<128, 256>>>(x, proj1_w, proj1_b, pa, pc);
    xg_kernel<<<2048, 128>>>(pa, pc, gru1_wih, gru1_bih, gru1_bhh, pxg);
    gru_scan_kernel<0><<<256, 128>>>(pxg, gru1_whh, gru1_bhh, nullptr, nullptr, ph1);
    // Stage 2
    pre_kernel<32><<<128, 256>>>(ph1, proj2_w, proj2_b, pa, pc);
    xg_kernel<<<2048, 128>>>(pa, pc, gru2_wih, gru2_bih, gru2_bhh, pxg);
    gru_scan_kernel<1><<<256, 128>>>(pxg, gru2_whh, gru2_bhh, clf_w, clf_b, out);
}

// round 12
// speedup vs baseline: 1.1658x; 1.1658x over previous
#include <cuda_runtime.h>
#include <cuda_bf16.h>
#include <cstdint>

#define NPTS 1024
#define HDIM 32

typedef unsigned long long u64;
typedef unsigned int u32;

// ---------- scratch ----------
__device__ float g_a[NPTS * HDIM];
__device__ float g_c[(NPTS + 4) * HDIM];          // +4 zero pad rows
__device__ float g_h1[NPTS * HDIM];
__device__ float g_xg[(size_t)NPTS * NPTS * 96];  // [i][j][96] = 384 MiB

// ---------- helpers ----------
__device__ __forceinline__ u64 f2fma(u64 a, u64 b, u64 c) {
    u64 d;
    asm("fma.rn.f32x2 %0, %1, %2, %3;" : "=l"(d) : "l"(a), "l"(b), "l"(c));
    return d;
}
__device__ __forceinline__ u64 add2(u64 a, u64 b) {
    u64 d;
    asm("add.rn.f32x2 %0, %1, %2;" : "=l"(d) : "l"(a), "l"(b));
    return d;
}
__device__ __forceinline__ u64 pack2(float lo, float hi) {
    u64 r;
    asm("mov.b64 %0, {%1, %2};" : "=l"(r) : "f"(lo), "f"(hi));
    return r;
}
__device__ __forceinline__ float hsum2(u64 v) {
    float lo, hi;
    asm("mov.b64 {%0, %1}, %2;" : "=f"(lo), "=f"(hi) : "l"(v));
    return lo + hi;
}
__device__ __forceinline__ float tanh_hw(float x) {
    float y;
    asm("tanh.approx.f32 %0, %1;" : "=f"(y) : "f"(x));
    return y;
}
__device__ __forceinline__ float sig_hw(float x) {
    return fmaf(tanh_hw(0.5f * x), 0.5f, 0.5f);
}
__device__ __forceinline__ u32 smem_u32(const void* p) {
    u32 a;
    asm("{ .reg .u64 t; cvta.to.shared.u64 t, %1; cvt.u32.u64 %0, t; }"
        : "=r"(a) : "l"(p));
    return a;
}
__device__ __forceinline__ void sts32(u32 addr, float v) {
    asm volatile("st.shared.b32 [%0], %1;" :: "r"(addr), "f"(v) : "memory");
}
__device__ __forceinline__ void lds_v2(u64& p0, u64& p1, u32 addr) {
    asm volatile("ld.shared.v2.u64 {%0, %1}, [%2];"
                 : "=l"(p0), "=l"(p1) : "r"(addr));
}
__device__ __forceinline__ u32 tf32_of(float x) {
    u32 r;
    asm("cvt.rna.tf32.f32 %0, %1;" : "=r"(r) : "f"(x));
    return r;
}
__device__ __forceinline__ void mma_tf32(float& c0, float& c1, float& c2, float& c3,
                                         u32 a0, u32 a1, u32 a2, u32 a3,
                                         u32 b0, u32 b1) {
    asm("mma.sync.aligned.m16n8k8.row.col.f32.tf32.tf32.f32 "
        "{%0,%1,%2,%3}, {%4,%5,%6,%7}, {%8,%9}, {%0,%1,%2,%3};"
        : "+f"(c0), "+f"(c1), "+f"(c2), "+f"(c3)
        : "r"(a0), "r"(a1), "r"(a2), "r"(a3), "r"(b0), "r"(b1));
}

// ---------- precompute: a_i = (Wa-Wb)@x_i + b ; c_j = Wb@x_j ----------
template <int F>
__global__ void __launch_bounds__(256)
pre_kernel(const float* __restrict__ x, const float* __restrict__ w,
           const float* __restrict__ b, float* __restrict__ a,
           float* __restrict__ c) {
    int wq = threadIdx.x >> 5;
    int l = threadIdx.x & 31;
    int i = blockIdx.x * 8 + wq;
    if (i >= NPTS) return;
    float av = b[l];
    float cv = 0.0f;
    const float* wr = w + l * (2 * F);
    const float* xr = x + i * F;
#pragma unroll
    for (int f = 0; f < F; ++f) {
        float xv = xr[f];
        float wa = wr[f];
        float wb = wr[F + f];
        av = fmaf(wa - wb, xv, av);
        cv = fmaf(wb, xv, cv);
    }
    a[i * HDIM + l] = av;
    c[i * HDIM + l] = cv;
}

// ---------- xg via tensor cores (tf32 MMA, A split hi/lo for accuracy) ----
// XG[i*1024+j, n] = sum_k relu(a_i[k]+c_j[k]) * wih[n,k] + Bv[n]
// Bv[n] = bih[n] + bhh[n] for n<64 (r,z gates), bih[n] for n>=64 (n gate).
// CTA = one i (8 warps); warp covers 128 j as 8 tiles of m16n8k8 MMAs.
__global__ void __launch_bounds__(256)
xg_mma_kernel(const float* __restrict__ a, const float* __restrict__ c,
              const float* __restrict__ wih, const float* __restrict__ bih,
              const float* __restrict__ bhh, float* __restrict__ xg) {
    const int lane = threadIdx.x & 31;
    const int warp = threadIdx.x >> 5;
    const int g = lane >> 2;       // groupID 0..7
    const int tig = lane & 3;      // thread-in-group 0..3
    const int i = blockIdx.x;
    const int jbase = warp * 128;

    // B fragments: b[nt][kc][2]; b0 = wih[nt*8+g][kc*8+tig], b1 = +4 col.
    u32 Bf[12][4][2];
#pragma unroll
    for (int nt = 0; nt < 12; ++nt) {
        const float* wr = wih + (nt * 8 + g) * HDIM;
#pragma unroll
        for (int kc = 0; kc < 4; ++kc) {
            Bf[nt][kc][0] = tf32_of(wr[kc * 8 + tig]);
            Bf[nt][kc][1] = tf32_of(wr[kc * 8 + tig + 4]);
        }
    }
    // Bias per n-tile at cols 2*tig, 2*tig+1.
    float bias0[12], bias1[12];
#pragma unroll
    for (int nt = 0; nt < 12; ++nt) {
        const int n0 = nt * 8 + 2 * tig;
        bias0[nt] = bih[n0] + (n0 < 64 ? bhh[n0] : 0.0f);
        bias1[nt] = bih[n0 + 1] + (n0 + 1 < 64 ? bhh[n0 + 1] : 0.0f);
    }
    // a_i values this thread needs: cols kc*8+tig and kc*8+tig+4.
    float av0[4], av1[4];
#pragma unroll
    for (int kc = 0; kc < 4; ++kc) {
        av0[kc] = a[i * HDIM + kc * 8 + tig];
        av1[kc] = a[i * HDIM + kc * 8 + tig + 4];
    }

    for (int t = 0; t < 8; ++t) {
        const int j0 = jbase + t * 16;
        const float* cr0 = c + (j0 + g) * HDIM;       // row g
        const float* cr1 = c + (j0 + g + 8) * HDIM;   // row g+8

        // accumulators (init with bias; rows share bias)
        float acc[12][4];
#pragma unroll
        for (int nt = 0; nt < 12; ++nt) {
            acc[nt][0] = bias0[nt];
            acc[nt][1] = bias1[nt];
            acc[nt][2] = bias0[nt];
            acc[nt][3] = bias1[nt];
        }

#pragma unroll
        for (int kc = 0; kc < 4; ++kc) {
            // U values for A fragment (row-major 16x8 tile, k = kc*8 + col)
            const float u0 = fmaxf(av0[kc] + cr0[kc * 8 + tig], 0.0f);       // a0
            const float u1 = fmaxf(av0[kc] + cr1[kc * 8 + tig], 0.0f);       // a1
            const float u2 = fmaxf(av1[kc] + cr0[kc * 8 + tig + 4], 0.0f);   // a2
            const float u3 = fmaxf(av1[kc] + cr1[kc * 8 + tig + 4], 0.0f);   // a3
            const u32 h0 = tf32_of(u0), h1 = tf32_of(u1);
            const u32 h2 = tf32_of(u2), h3 = tf32_of(u3);
            const u32 l0 = tf32_of(u0 - __uint_as_float(h0));
            const u32 l1 = tf32_of(u1 - __uint_as_float(h1));
            const u32 l2 = tf32_of(u2 - __uint_as_float(h2));
            const u32 l3 = tf32_of(u3 - __uint_as_float(h3));
#pragma unroll
            for (int nt = 0; nt < 12; ++nt) {
                mma_tf32(acc[nt][0], acc[nt][1], acc[nt][2], acc[nt][3],
                         h0, h1, h2, h3, Bf[nt][kc][0], Bf[nt][kc][1]);
                mma_tf32(acc[nt][0], acc[nt][1], acc[nt][2], acc[nt][3],
                         l0, l1, l2, l3, Bf[nt][kc][0], Bf[nt][kc][1]);
            }
        }

        // store: row0 = i*1024 + j0 + g, row1 = +8; col = nt*8 + 2*tig
        float* out0 = xg + ((size_t)i * NPTS + j0 + g) * 96;
        float* out1 = out0 + (size_t)8 * 96;
#pragma unroll
        for (int nt = 0; nt < 12; ++nt) {
            const int col = nt * 8 + 2 * tig;
            *reinterpret_cast<float2*>(out0 + col) = make_float2(acc[nt][0], acc[nt][1]);
            *reinterpret_cast<float2*>(out1 + col) = make_float2(acc[nt][2], acc[nt][3]);
        }
    }
}

// ---------- GRU scan: recurrence only (hg matvec + tail), xg streamed ------
template <int FUSE_CLF>
__global__ void __launch_bounds__(128)
gru_scan_kernel(const float* __restrict__ xg, const float* __restrict__ whh,
                const float* __restrict__ bhh,
                const float* __restrict__ clf_w, const float* __restrict__ clf_b,
                float* __restrict__ out) {
    __shared__ __align__(16) float s_h[4][2][HDIM];

    const int w = threadIdx.x >> 5;
    const int l = threadIdx.x & 31;
    const int i = blockIdx.x * 4 + w;

    u64 Whr[16], Whz[16], Whn[16];
    {
        const u64* pr = (const u64*)(whh + (0 * HDIM + l) * HDIM);
        const u64* pz = (const u64*)(whh + (1 * HDIM + l) * HDIM);
        const u64* pn = (const u64*)(whh + (2 * HDIM + l) * HDIM);
#pragma unroll
        for (int q = 0; q < 16; ++q) {
            Whr[q] = pr[q];
            Whz[q] = pz[q];
            Whn[q] = pn[q];
        }
    }
    const u64 init_n = pack2(bhh[2 * HDIM + l], 0.0f);   // b_hn

    const float* xin = xg + (size_t)i * NPTS * 96 + l;
    const u32 hb = smem_u32(&s_h[w][0][0]);

    // prefetch pipeline, distance 4
    float pr_[4], pz_[4], pn_[4];
#pragma unroll
    for (int t = 0; t < 4; ++t) {
        pr_[t] = xin[t * 96];
        pz_[t] = xin[t * 96 + 32];
        pn_[t] = xin[t * 96 + 64];
    }

    float h = 0.0f;

    for (int j = 0; j < NPTS; j += 4) {
#pragma unroll
        for (int s = 0; s < 4; ++s) {
            const int jj = j + s;
            const float xr = pr_[s];
            const float xz = pz_[s];
            const float xn = pn_[s];
            const int jn = (jj + 4 < NPTS) ? (jj + 4) : jj;   // clamp; dup harmless
            pr_[s] = xin[jn * 96];
            pz_[s] = xin[jn * 96 + 32];
            pn_[s] = xin[jn * 96 + 64];

            const u32 ho = hb + (u32)(s & 1) * 128u;
            sts32(ho + l * 4u, h);
            __syncwarp();
            u64 r0 = 0ULL, r1 = 0ULL, z0 = 0ULL, z1 = 0ULL;
            u64 n0 = init_n, n1 = 0ULL;
#pragma unroll
            for (int q = 0; q < 8; ++q) {
                u64 p0, p1;
                lds_v2(p0, p1, ho + q * 16u);
                r0 = f2fma(Whr[2 * q], p0, r0);
                r1 = f2fma(Whr[2 * q + 1], p1, r1);
                z0 = f2fma(Whz[2 * q], p0, z0);
                z1 = f2fma(Whz[2 * q + 1], p1, z1);
                n0 = f2fma(Whn[2 * q], p0, n0);
                n1 = f2fma(Whn[2 * q + 1], p1, n1);
            }
            const float r = sig_hw(xr + hsum2(add2(r0, r1)));
            const float z = sig_hw(xz + hsum2(add2(z0, z1)));
            const float n = tanh_hw(fmaf(r, hsum2(add2(n0, n1)), xn));
            h = fmaf(z, h - n, n);
        }
    }

    if (FUSE_CLF) {
        sts32(hb + l * 4u, h);
        __syncwarp();
        if (l < 3) {
            float acc = clf_b[l];
            const float* cw = clf_w + l * HDIM;
#pragma unroll
            for (int hh = 0; hh < HDIM; ++hh)
                acc = fmaf(cw[hh], s_h[w][0][hh], acc);
            out[i * 3 + l] = acc;
        }
    } else {
        out[i * HDIM + l] = h;
    }
}

extern "C" void kernel_launch(void* const* d_in, const int* in_sizes, int n_in,
                              void* d_out, int out_size) {
    const float* x        = (const float*)d_in[0];
    const float* proj1_w  = (const float*)d_in[1];
    const float* proj1_b  = (const float*)d_in[2];
    const float* gru1_wih = (const float*)d_in[3];
    const float* gru1_whh = (const float*)d_in[4];
    const float* gru1_bih = (const float*)d_in[5];
    const float* gru1_bhh = (const float*)d_in[6];
    const float* proj2_w  = (const float*)d_in[7];
    const float* proj2_b  = (const float*)d_in[8];
    const float* gru2_wih = (const float*)d_in[9];
    const float* gru2_whh = (const float*)d_in[10];
    const float* gru2_bih = (const float*)d_in[11];
    const float* gru2_bhh = (const float*)d_in[12];
    const float* clf_w    = (const float*)d_in[13];
    const float* clf_b    = (const float*)d_in[14];
    float* out = (float*)d_out;

    float *pa, *pc, *ph1, *pxg;
    cudaGetSymbolAddress((void**)&pa, g_a);
    cudaGetSymbolAddress((void**)&pc, g_c);
    cudaGetSymbolAddress((void**)&ph1, g_h1);
    cudaGetSymbolAddress((void**)&pxg, g_xg);

    // Stage 1
    pre_kernel<16><<<128, 256>>>(x, proj1_w, proj1_b, pa, pc);
    xg_mma_kernel<<<1024, 256>>>(pa, pc, gru1_wih, gru1_bih, gru1_bhh, pxg);
    gru_scan_kernel<0><<<256, 128>>>(pxg, gru1_whh, gru1_bhh, nullptr, nullptr, ph1);
    // Stage 2
    pre_kernel<32><<<128, 256>>>(ph1, proj2_w, proj2_b, pa, pc);
    xg_mma_kernel<<<1024, 256>>>(pa, pc, gru2_wih, gru2_bih, gru2_bhh, pxg);
    gru_scan_kernel<1><<<256, 128>>>(pxg, gru2_whh, gru2_bhh, clf_w, clf_b, out);
}

// round 13
// speedup vs baseline: 1.4632x; 1.2550x over previous
#include <cuda_runtime.h>
#include <cuda_bf16.h>
#include <cstdint>

#define NPTS 1024
#define HDIM 32
#define TCH 8
#define NCH (NPTS / TCH)      // 128 chunks
#define ROWB 400u             // 100 floats per (seq,t) row (bank-spread pad)
#define SEQB (8u * ROWB)      // 3200 B
#define BUFB (4u * SEQB)      // 12800 B

typedef unsigned long long u64;
typedef unsigned int u32;

// ---------- scratch ----------
__device__ float g_a[NPTS * HDIM];
__device__ float g_c[(NPTS + 4) * HDIM];
__device__ float g_h1[NPTS * HDIM];

// ---------- helpers ----------
__device__ __forceinline__ u64 f2fma(u64 a, u64 b, u64 c) {
    u64 d;
    asm("fma.rn.f32x2 %0, %1, %2, %3;" : "=l"(d) : "l"(a), "l"(b), "l"(c));
    return d;
}
__device__ __forceinline__ u64 add2(u64 a, u64 b) {
    u64 d;
    asm("add.rn.f32x2 %0, %1, %2;" : "=l"(d) : "l"(a), "l"(b));
    return d;
}
__device__ __forceinline__ u64 pack2(float lo, float hi) {
    u64 r;
    asm("mov.b64 %0, {%1, %2};" : "=l"(r) : "f"(lo), "f"(hi));
    return r;
}
__device__ __forceinline__ float hsum2(u64 v) {
    float lo, hi;
    asm("mov.b64 {%0, %1}, %2;" : "=f"(lo), "=f"(hi) : "l"(v));
    return lo + hi;
}
__device__ __forceinline__ float tanh_hw(float x) {
    float y;
    asm("tanh.approx.f32 %0, %1;" : "=f"(y) : "f"(x));
    return y;
}
__device__ __forceinline__ float sig_hw(float x) {
    return fmaf(tanh_hw(0.5f * x), 0.5f, 0.5f);
}
__device__ __forceinline__ u32 smem_u32(const void* p) {
    u32 a;
    asm("{ .reg .u64 t; cvta.to.shared.u64 t, %1; cvt.u32.u64 %0, t; }"
        : "=r"(a) : "l"(p));
    return a;
}
__device__ __forceinline__ void sts32(u32 addr, float v) {
    asm volatile("st.shared.b32 [%0], %1;" :: "r"(addr), "f"(v) : "memory");
}
__device__ __forceinline__ void sts64(u32 addr, u64 v) {
    asm volatile("st.shared.b64 [%0], %1;" :: "r"(addr), "l"(v) : "memory");
}
__device__ __forceinline__ float lds32f(u32 addr) {
    float v;
    asm volatile("ld.shared.b32 %0, [%1];" : "=f"(v) : "r"(addr));
    return v;
}
__device__ __forceinline__ void lds_v2(u64& p0, u64& p1, u32 addr) {
    asm volatile("ld.shared.v2.u64 {%0, %1}, [%2];"
                 : "=l"(p0), "=l"(p1) : "r"(addr));
}
__device__ __forceinline__ u32 tf32_of(float x) {
    u32 r;
    asm("cvt.rna.tf32.f32 %0, %1;" : "=r"(r) : "f"(x));
    return r;
}
__device__ __forceinline__ void mma_tf32(float& c0, float& c1, float& c2, float& c3,
                                         u32 a0, u32 a1, u32 a2, u32 a3,
                                         u32 b0, u32 b1) {
    asm("mma.sync.aligned.m16n8k8.row.col.f32.tf32.tf32.f32 "
        "{%0,%1,%2,%3}, {%4,%5,%6,%7}, {%8,%9}, {%0,%1,%2,%3};"
        : "+f"(c0), "+f"(c1), "+f"(c2), "+f"(c3)
        : "r"(a0), "r"(a1), "r"(a2), "r"(a3), "r"(b0), "r"(b1));
}
__device__ __forceinline__ void bar_all() {
    asm volatile("bar.sync 0;" ::: "memory");
}

// ---------- precompute: a_i = (Wa-Wb)@x_i + b ; c_j = Wb@x_j ----------
template <int F>
__global__ void __launch_bounds__(256)
pre_kernel(const float* __restrict__ x, const float* __restrict__ w,
           const float* __restrict__ b, float* __restrict__ a,
           float* __restrict__ c) {
    int wq = threadIdx.x >> 5;
    int l = threadIdx.x & 31;
    int i = blockIdx.x * 8 + wq;
    if (i >= NPTS) return;
    float av = b[l];
    float cv = 0.0f;
    const float* wr = w + l * (2 * F);
    const float* xr = x + i * F;
#pragma unroll
    for (int f = 0; f < F; ++f) {
        float xv = xr[f];
        float wa = wr[f];
        float wb = wr[F + f];
        av = fmaf(wa - wb, xv, av);
        cv = fmaf(wb, xv, cv);
    }
    a[i * HDIM + l] = av;
    c[i * HDIM + l] = cv;
}

// ---------- fused GRU: MMA producers + recurrence consumers ----------
// 192 threads: warps 0-3 consumers (seq i = blk*4+w), warps 4-5 producers.
// Producer pw serves seqs {2pw, 2pw+1}: one m16n8k8 tile per chunk has
// rows 0-7 = seq s0 (j = j0+row), rows 8-15 = seq s1 (same j's).
// xg tiles live only in a 25.6 KB smem ring; no HBM traffic.
template <int FUSE_CLF>
__global__ void __launch_bounds__(192, 2)
gru_fused_kernel(const float* __restrict__ a, const float* __restrict__ c,
                 const float* __restrict__ wih, const float* __restrict__ whh,
                 const float* __restrict__ bih, const float* __restrict__ bhh,
                 const float* __restrict__ clf_w, const float* __restrict__ clf_b,
                 float* __restrict__ out) {
    __shared__ __align__(16) float s_xg[2][4][TCH][100];  // ring: 25600 B
    __shared__ __align__(16) float s_h[4][2][HDIM];

    const int wid = threadIdx.x >> 5;
    const int l = threadIdx.x & 31;
    const u32 xgb = smem_u32(&s_xg[0][0][0][0]);

    if (wid < 4) {
        // ===================== consumer =====================
        const int w = wid;
        const int i = blockIdx.x * 4 + w;

        u64 Whr[16], Whz[16], Whn[16];
        {
            const u64* pr = (const u64*)(whh + (0 * HDIM + l) * HDIM);
            const u64* pz = (const u64*)(whh + (1 * HDIM + l) * HDIM);
            const u64* pn = (const u64*)(whh + (2 * HDIM + l) * HDIM);
#pragma unroll
            for (int q = 0; q < 16; ++q) {
                Whr[q] = pr[q];
                Whz[q] = pz[q];
                Whn[q] = pn[q];
            }
        }
        const u64 init_r = pack2(bih[l] + bhh[l], 0.0f);
        const u64 init_z = pack2(bih[HDIM + l] + bhh[HDIM + l], 0.0f);
        const u64 init_n = pack2(bhh[2 * HDIM + l], 0.0f);  // b_hn
        const float b_xn = bih[2 * HDIM + l];

        const u32 hb = smem_u32(&s_h[w][0][0]);
        const u32 xseq = xgb + (u32)w * SEQB;

        float h = 0.0f;

        for (int k = 0; k <= NCH; ++k) {
            if (k > 0) {
                const u32 xc = xseq + (u32)((k - 1) & 1) * BUFB;
#pragma unroll
                for (int t = 0; t < TCH; ++t) {
                    const float xr = lds32f(xc + t * ROWB + l * 4u);
                    const float xz = lds32f(xc + t * ROWB + 128u + l * 4u);
                    const float xn = lds32f(xc + t * ROWB + 256u + l * 4u);
                    const u32 ho = hb + (u32)(t & 1) * 128u;
                    sts32(ho + l * 4u, h);
                    __syncwarp();
                    u64 r0 = init_r, r1 = 0ULL, z0 = init_z, z1 = 0ULL;
                    u64 n0 = init_n, n1 = 0ULL;
#pragma unroll
                    for (int q = 0; q < 8; ++q) {
                        u64 p0, p1;
                        lds_v2(p0, p1, ho + q * 16u);
                        r0 = f2fma(Whr[2 * q], p0, r0);
                        r1 = f2fma(Whr[2 * q + 1], p1, r1);
                        z0 = f2fma(Whz[2 * q], p0, z0);
                        z1 = f2fma(Whz[2 * q + 1], p1, z1);
                        n0 = f2fma(Whn[2 * q], p0, n0);
                        n1 = f2fma(Whn[2 * q + 1], p1, n1);
                    }
                    const float r = sig_hw(xr + hsum2(add2(r0, r1)));
                    const float z = sig_hw(xz + hsum2(add2(z0, z1)));
                    const float n = tanh_hw(fmaf(r, hsum2(add2(n0, n1)), xn + b_xn));
                    h = fmaf(z, h - n, n);
                }
            }
            bar_all();
        }

        if (FUSE_CLF) {
            sts32(hb + l * 4u, h);
            __syncwarp();
            if (l < 3) {
                float acc = clf_b[l];
                const float* cw = clf_w + l * HDIM;
#pragma unroll
                for (int hh = 0; hh < HDIM; ++hh)
                    acc = fmaf(cw[hh], s_h[w][0][hh], acc);
                out[i * 3 + l] = acc;
            }
        } else {
            out[i * HDIM + l] = h;
        }
    } else {
        // ===================== producer =====================
        const int pw = wid - 4;            // 0 or 1
        const int s0 = pw * 2, s1 = s0 + 1;
        const int g = l >> 2, tig = l & 3;

        // B fragments: wih rows n = nt*8+g, cols k = kc*8+tig (+4)
        u32 Bf[12][4][2];
#pragma unroll
        for (int nt = 0; nt < 12; ++nt) {
            const float* wr = wih + (nt * 8 + g) * HDIM;
#pragma unroll
            for (int kc = 0; kc < 4; ++kc) {
                Bf[nt][kc][0] = tf32_of(wr[kc * 8 + tig]);
                Bf[nt][kc][1] = tf32_of(wr[kc * 8 + tig + 4]);
            }
        }
        const int i0 = blockIdx.x * 4 + s0;
        const int i1 = i0 + 1;
        float av00[4], av01[4], av10[4], av11[4];
#pragma unroll
        for (int kc = 0; kc < 4; ++kc) {
            av00[kc] = a[i0 * HDIM + kc * 8 + tig];
            av01[kc] = a[i0 * HDIM + kc * 8 + tig + 4];
            av10[kc] = a[i1 * HDIM + kc * 8 + tig];
            av11[kc] = a[i1 * HDIM + kc * 8 + tig + 4];
        }

        for (int k = 0; k <= NCH; ++k) {
            if (k < NCH) {
                const int j0 = k * TCH;
                const float* cr = c + (j0 + g) * HDIM;
                const u32 base0 = xgb + (u32)(k & 1) * BUFB + (u32)s0 * SEQB + (u32)g * ROWB;
                const u32 base1 = xgb + (u32)(k & 1) * BUFB + (u32)s1 * SEQB + (u32)g * ROWB;
#pragma unroll
                for (int half = 0; half < 2; ++half) {
                    float acc[6][4];
#pragma unroll
                    for (int nn = 0; nn < 6; ++nn) {
                        acc[nn][0] = 0.0f; acc[nn][1] = 0.0f;
                        acc[nn][2] = 0.0f; acc[nn][3] = 0.0f;
                    }
#pragma unroll
                    for (int kc = 0; kc < 4; ++kc) {
                        const float cv0 = cr[kc * 8 + tig];
                        const float cv1 = cr[kc * 8 + tig + 4];
                        const float u0 = fmaxf(av00[kc] + cv0, 0.0f);  // row g    (s0)
                        const float u1 = fmaxf(av10[kc] + cv0, 0.0f);  // row g+8  (s1)
                        const float u2 = fmaxf(av01[kc] + cv1, 0.0f);  // row g  col+4
                        const float u3 = fmaxf(av11[kc] + cv1, 0.0f);  // row g+8 col+4
                        const u32 h0 = tf32_of(u0), h1 = tf32_of(u1);
                        const u32 h2 = tf32_of(u2), h3 = tf32_of(u3);
                        const u32 lo0 = tf32_of(u0 - __uint_as_float(h0));
                        const u32 lo1 = tf32_of(u1 - __uint_as_float(h1));
                        const u32 lo2 = tf32_of(u2 - __uint_as_float(h2));
                        const u32 lo3 = tf32_of(u3 - __uint_as_float(h3));
#pragma unroll
                        for (int nn = 0; nn < 6; ++nn) {
                            const int nt = half * 6 + nn;
                            mma_tf32(acc[nn][0], acc[nn][1], acc[nn][2], acc[nn][3],
                                     h0, h1, h2, h3, Bf[nt][kc][0], Bf[nt][kc][1]);
                            mma_tf32(acc[nn][0], acc[nn][1], acc[nn][2], acc[nn][3],
                                     lo0, lo1, lo2, lo3, Bf[nt][kc][0], Bf[nt][kc][1]);
                        }
                    }
#pragma unroll
                    for (int nn = 0; nn < 6; ++nn) {
                        const int nt = half * 6 + nn;
                        const u32 cb = (u32)(nt * 8 + 2 * tig) * 4u;
                        sts64(base0 + cb, pack2(acc[nn][0], acc[nn][1]));  // seq s0, t=g
                        sts64(base1 + cb, pack2(acc[nn][2], acc[nn][3]));  // seq s1, t=g
                    }
                }
            }
            bar_all();
        }
    }
}

extern "C" void kernel_launch(void* const* d_in, const int* in_sizes, int n_in,
                              void* d_out, int out_size) {
    const float* x        = (const float*)d_in[0];
    const float* proj1_w  = (const float*)d_in[1];
    const float* proj1_b  = (const float*)d_in[2];
    const float* gru1_wih = (const float*)d_in[3];
    const float* gru1_whh = (const float*)d_in[4];
    const float* gru1_bih = (const float*)d_in[5];
    const float* gru1_bhh = (const float*)d_in[6];
    const float* proj2_w  = (const float*)d_in[7];
    const float* proj2_b  = (const float*)d_in[8];
    const float* gru2_wih = (const float*)d_in[9];
    const float* gru2_whh = (const float*)d_in[10];
    const float* gru2_bih = (const float*)d_in[11];
    const float* gru2_bhh = (const float*)d_in[12];
    const float* clf_w    = (const float*)d_in[13];
    const float* clf_b    = (const float*)d_in[14];
    float* out = (float*)d_out;

    float *pa, *pc, *ph1;
    cudaGetSymbolAddress((void**)&pa, g_a);
    cudaGetSymbolAddress((void**)&pc, g_c);
    cudaGetSymbolAddress((void**)&ph1, g_h1);

    // Stage 1
    pre_kernel<16><<<128, 256>>>(x, proj1_w, proj1_b, pa, pc);
    gru_fused_kernel<0><<<256, 192>>>(pa, pc, gru1_wih, gru1_whh, gru1_bih,
                                      gru1_bhh, nullptr, nullptr, ph1);
    // Stage 2
    pre_kernel<32><<<128, 256>>>(ph1, proj2_w, proj2_b, pa, pc);
    gru_fused_kernel<1><<<256, 192>>>(pa, pc, gru2_wih, gru2_whh, gru2_bih,
                                      gru2_bhh, clf_w, clf_b, out);
}

// round 14
// speedup vs baseline: 1.5740x; 1.0757x over previous
#include <cuda_runtime.h>
#include <cuda_bf16.h>
#include <cstdint>

#define NPTS 1024
#define HDIM 32
#define TCH 8
#define NCH (NPTS / TCH)      // 128 chunks
#define ROWB 400u             // 100 floats per (seq,t) row
#define SEQB (8u * ROWB)      // 3200 B
#define BUFB (8u * SEQB)      // 25600 B (8 seqs per CTA)

typedef unsigned long long u64;
typedef unsigned int u32;

// ---------- scratch ----------
__device__ float g_a[NPTS * HDIM];
__device__ float g_c[(NPTS + 4) * HDIM];
__device__ float g_h1[NPTS * HDIM];

// ---------- helpers ----------
__device__ __forceinline__ u64 f2fma(u64 a, u64 b, u64 c) {
    u64 d;
    asm("fma.rn.f32x2 %0, %1, %2, %3;" : "=l"(d) : "l"(a), "l"(b), "l"(c));
    return d;
}
__device__ __forceinline__ u64 add2(u64 a, u64 b) {
    u64 d;
    asm("add.rn.f32x2 %0, %1, %2;" : "=l"(d) : "l"(a), "l"(b));
    return d;
}
__device__ __forceinline__ u64 pack2(float lo, float hi) {
    u64 r;
    asm("mov.b64 %0, {%1, %2};" : "=l"(r) : "f"(lo), "f"(hi));
    return r;
}
__device__ __forceinline__ float hsum2(u64 v) {
    float lo, hi;
    asm("mov.b64 {%0, %1}, %2;" : "=f"(lo), "=f"(hi) : "l"(v));
    return lo + hi;
}
__device__ __forceinline__ float tanh_hw(float x) {
    float y;
    asm("tanh.approx.f32 %0, %1;" : "=f"(y) : "f"(x));
    return y;
}
__device__ __forceinline__ float sig_hw(float x) {
    return fmaf(tanh_hw(0.5f * x), 0.5f, 0.5f);
}
__device__ __forceinline__ u32 smem_u32(const void* p) {
    u32 a;
    asm("{ .reg .u64 t; cvta.to.shared.u64 t, %1; cvt.u32.u64 %0, t; }"
        : "=r"(a) : "l"(p));
    return a;
}
__device__ __forceinline__ void sts32(u32 addr, float v) {
    asm volatile("st.shared.b32 [%0], %1;" :: "r"(addr), "f"(v) : "memory");
}
__device__ __forceinline__ void sts64(u32 addr, u64 v) {
    asm volatile("st.shared.b64 [%0], %1;" :: "r"(addr), "l"(v) : "memory");
}
__device__ __forceinline__ float lds32f(u32 addr) {
    float v;
    asm volatile("ld.shared.b32 %0, [%1];" : "=f"(v) : "r"(addr));
    return v;
}
__device__ __forceinline__ void lds_v2(u64& p0, u64& p1, u32 addr) {
    asm volatile("ld.shared.v2.u64 {%0, %1}, [%2];"
                 : "=l"(p0), "=l"(p1) : "r"(addr));
}
__device__ __forceinline__ u32 tf32_of(float x) {
    u32 r;
    asm("cvt.rna.tf32.f32 %0, %1;" : "=r"(r) : "f"(x));
    return r;
}
__device__ __forceinline__ void mma_tf32(float& c0, float& c1, float& c2, float& c3,
                                         u32 a0, u32 a1, u32 a2, u32 a3,
                                         u32 b0, u32 b1) {
    asm("mma.sync.aligned.m16n8k8.row.col.f32.tf32.tf32.f32 "
        "{%0,%1,%2,%3}, {%4,%5,%6,%7}, {%8,%9}, {%0,%1,%2,%3};"
        : "+f"(c0), "+f"(c1), "+f"(c2), "+f"(c3)
        : "r"(a0), "r"(a1), "r"(a2), "r"(a3), "r"(b0), "r"(b1));
}
__device__ __forceinline__ void bar_all() {
    asm volatile("bar.sync 0;" ::: "memory");
}

// ---------- precompute: a_i = (Wa-Wb)@x_i + b ; c_j = Wb@x_j ----------
template <int F>
__global__ void __launch_bounds__(256)
pre_kernel(const float* __restrict__ x, const float* __restrict__ w,
           const float* __restrict__ b, float* __restrict__ a,
           float* __restrict__ c) {
    int wq = threadIdx.x >> 5;
    int l = threadIdx.x & 31;
    int i = blockIdx.x * 8 + wq;
    if (i >= NPTS) return;
    float av = b[l];
    float cv = 0.0f;
    const float* wr = w + l * (2 * F);
    const float* xr = x + i * F;
#pragma unroll
    for (int f = 0; f < F; ++f) {
        float xv = xr[f];
        float wa = wr[f];
        float wb = wr[F + f];
        av = fmaf(wa - wb, xv, av);
        cv = fmaf(wb, xv, cv);
    }
    a[i * HDIM + l] = av;
    c[i * HDIM + l] = cv;
}

// ---------- fused GRU: MMA producers + 2-seq consumers ----------
// 256 threads: warps 0-3 consumers (2 seqs each), warps 4-7 producers (2 seqs).
// Consumer w handles seqs {2w, 2w+1}; producer pw=wid-4 produces the same pair.
// wid%4 mapping puts exactly 1 consumer + 1 producer on each SMSP.
// Two independent recurrence chains per consumer warp -> static ILP hides
// the LDS/MUFU chain latency without relying on the warp arbiter.
template <int FUSE_CLF>
__global__ void __launch_bounds__(256, 1)
gru_fused_kernel(const float* __restrict__ a, const float* __restrict__ c,
                 const float* __restrict__ wih, const float* __restrict__ whh,
                 const float* __restrict__ bih, const float* __restrict__ bhh,
                 const float* __restrict__ clf_w, const float* __restrict__ clf_b,
                 float* __restrict__ out) {
    __shared__ __align__(16) float s_xg[2][8][TCH][100];  // ring: 51200 B
    __shared__ __align__(16) float s_h[8][2][HDIM];

    const int wid = threadIdx.x >> 5;
    const int l = threadIdx.x & 31;
    const u32 xgb = smem_u32(&s_xg[0][0][0][0]);

    if (wid < 4) {
        // ===================== consumer (2 sequences) =====================
        const int w = wid;
        const int sA = 2 * w, sB = sA + 1;
        const int iA = blockIdx.x * 8 + sA;
        const int iB = iA + 1;

        u64 Whr[16], Whz[16], Whn[16];
        {
            const u64* pr = (const u64*)(whh + (0 * HDIM + l) * HDIM);
            const u64* pz = (const u64*)(whh + (1 * HDIM + l) * HDIM);
            const u64* pn = (const u64*)(whh + (2 * HDIM + l) * HDIM);
#pragma unroll
            for (int q = 0; q < 16; ++q) {
                Whr[q] = pr[q];
                Whz[q] = pz[q];
                Whn[q] = pn[q];
            }
        }
        const u64 init_r = pack2(bih[l] + bhh[l], 0.0f);
        const u64 init_z = pack2(bih[HDIM + l] + bhh[HDIM + l], 0.0f);
        const u64 init_n = pack2(bhh[2 * HDIM + l], 0.0f);  // b_hn
        const float b_xn = bih[2 * HDIM + l];

        const u32 hbA = smem_u32(&s_h[sA][0][0]);
        const u32 hbB = smem_u32(&s_h[sB][0][0]);
        const u32 xA = xgb + (u32)sA * SEQB;
        const u32 xB = xgb + (u32)sB * SEQB;

        float hA = 0.0f, hB = 0.0f;

        for (int k = 0; k <= NCH; ++k) {
            if (k > 0) {
                const u32 boff = (u32)((k - 1) & 1) * BUFB;
                const u32 xcA = xA + boff;
                const u32 xcB = xB + boff;
#pragma unroll
                for (int t = 0; t < TCH; ++t) {
                    const u32 ro = (u32)t * ROWB + (u32)l * 4u;
                    const float xrA = lds32f(xcA + ro);
                    const float xzA = lds32f(xcA + ro + 128u);
                    const float xnA = lds32f(xcA + ro + 256u);
                    const float xrB = lds32f(xcB + ro);
                    const float xzB = lds32f(xcB + ro + 128u);
                    const float xnB = lds32f(xcB + ro + 256u);

                    const u32 po = (u32)(t & 1) * 128u;
                    sts32(hbA + po + l * 4u, hA);
                    sts32(hbB + po + l * 4u, hB);
                    __syncwarp();

                    u64 rA0 = init_r, rA1 = 0ULL, zA0 = init_z, zA1 = 0ULL;
                    u64 nA0 = init_n, nA1 = 0ULL;
                    u64 rB0 = init_r, rB1 = 0ULL, zB0 = init_z, zB1 = 0ULL;
                    u64 nB0 = init_n, nB1 = 0ULL;
#pragma unroll
                    for (int q = 0; q < 8; ++q) {
                        u64 pa0, pa1, pb0, pb1;
                        lds_v2(pa0, pa1, hbA + po + q * 16u);
                        lds_v2(pb0, pb1, hbB + po + q * 16u);
                        rA0 = f2fma(Whr[2 * q], pa0, rA0);
                        rA1 = f2fma(Whr[2 * q + 1], pa1, rA1);
                        rB0 = f2fma(Whr[2 * q], pb0, rB0);
                        rB1 = f2fma(Whr[2 * q + 1], pb1, rB1);
                        zA0 = f2fma(Whz[2 * q], pa0, zA0);
                        zA1 = f2fma(Whz[2 * q + 1], pa1, zA1);
                        zB0 = f2fma(Whz[2 * q], pb0, zB0);
                        zB1 = f2fma(Whz[2 * q + 1], pb1, zB1);
                        nA0 = f2fma(Whn[2 * q], pa0, nA0);
                        nA1 = f2fma(Whn[2 * q + 1], pa1, nA1);
                        nB0 = f2fma(Whn[2 * q], pb0, nB0);
                        nB1 = f2fma(Whn[2 * q + 1], pb1, nB1);
                    }
                    const float rA = sig_hw(xrA + hsum2(add2(rA0, rA1)));
                    const float rB = sig_hw(xrB + hsum2(add2(rB0, rB1)));
                    const float zA = sig_hw(xzA + hsum2(add2(zA0, zA1)));
                    const float zB = sig_hw(xzB + hsum2(add2(zB0, zB1)));
                    const float nA = tanh_hw(fmaf(rA, hsum2(add2(nA0, nA1)), xnA + b_xn));
                    const float nB = tanh_hw(fmaf(rB, hsum2(add2(nB0, nB1)), xnB + b_xn));
                    hA = fmaf(zA, hA - nA, nA);
                    hB = fmaf(zB, hB - nB, nB);
                }
            }
            bar_all();
        }

        if (FUSE_CLF) {
            sts32(hbA + l * 4u, hA);
            sts32(hbB + l * 4u, hB);
            __syncwarp();
            if (l < 3) {
                float accA = clf_b[l];
                float accB = clf_b[l];
                const float* cw = clf_w + l * HDIM;
#pragma unroll
                for (int hh = 0; hh < HDIM; ++hh) {
                    accA = fmaf(cw[hh], s_h[sA][0][hh], accA);
                    accB = fmaf(cw[hh], s_h[sB][0][hh], accB);
                }
                out[iA * 3 + l] = accA;
                out[iB * 3 + l] = accB;
            }
        } else {
            out[iA * HDIM + l] = hA;
            out[iB * HDIM + l] = hB;
        }
    } else {
        // ===================== producer (MMA, 2 sequences) =====================
        const int pw = wid - 4;            // 0..3
        const int s0 = pw * 2, s1 = s0 + 1;
        const int g = l >> 2, tig = l & 3;

        u32 Bf[12][4][2];
#pragma unroll
        for (int nt = 0; nt < 12; ++nt) {
            const float* wr = wih + (nt * 8 + g) * HDIM;
#pragma unroll
            for (int kc = 0; kc < 4; ++kc) {
                Bf[nt][kc][0] = tf32_of(wr[kc * 8 + tig]);
                Bf[nt][kc][1] = tf32_of(wr[kc * 8 + tig + 4]);
            }
        }
        const int i0 = blockIdx.x * 8 + s0;
        const int i1 = i0 + 1;
        float av00[4], av01[4], av10[4], av11[4];
#pragma unroll
        for (int kc = 0; kc < 4; ++kc) {
            av00[kc] = a[i0 * HDIM + kc * 8 + tig];
            av01[kc] = a[i0 * HDIM + kc * 8 + tig + 4];
            av10[kc] = a[i1 * HDIM + kc * 8 + tig];
            av11[kc] = a[i1 * HDIM + kc * 8 + tig + 4];
        }

        for (int k = 0; k <= NCH; ++k) {
            if (k < NCH) {
                const int j0 = k * TCH;
                const float* cr = c + (j0 + g) * HDIM;
                const u32 base0 = xgb + (u32)(k & 1) * BUFB + (u32)s0 * SEQB + (u32)g * ROWB;
                const u32 base1 = xgb + (u32)(k & 1) * BUFB + (u32)s1 * SEQB + (u32)g * ROWB;
#pragma unroll
                for (int half = 0; half < 2; ++half) {
                    float acc[6][4];
#pragma unroll
                    for (int nn = 0; nn < 6; ++nn) {
                        acc[nn][0] = 0.0f; acc[nn][1] = 0.0f;
                        acc[nn][2] = 0.0f; acc[nn][3] = 0.0f;
                    }
#pragma unroll
                    for (int kc = 0; kc < 4; ++kc) {
                        const float cv0 = cr[kc * 8 + tig];
                        const float cv1 = cr[kc * 8 + tig + 4];
                        const float u0 = fmaxf(av00[kc] + cv0, 0.0f);  // row g    (s0)
                        const float u1 = fmaxf(av10[kc] + cv0, 0.0f);  // row g+8  (s1)
                        const float u2 = fmaxf(av01[kc] + cv1, 0.0f);
                        const float u3 = fmaxf(av11[kc] + cv1, 0.0f);
                        const u32 h0 = tf32_of(u0), h1 = tf32_of(u1);
                        const u32 h2 = tf32_of(u2), h3 = tf32_of(u3);
                        const u32 lo0 = tf32_of(u0 - __uint_as_float(h0));
                        const u32 lo1 = tf32_of(u1 - __uint_as_float(h1));
                        const u32 lo2 = tf32_of(u2 - __uint_as_float(h2));
                        const u32 lo3 = tf32_of(u3 - __uint_as_float(h3));
#pragma unroll
                        for (int nn = 0; nn < 6; ++nn) {
                            const int nt = half * 6 + nn;
                            mma_tf32(acc[nn][0], acc[nn][1], acc[nn][2], acc[nn][3],
                                     h0, h1, h2, h3, Bf[nt][kc][0], Bf[nt][kc][1]);
                            mma_tf32(acc[nn][0], acc[nn][1], acc[nn][2], acc[nn][3],
                                     lo0, lo1, lo2, lo3, Bf[nt][kc][0], Bf[nt][kc][1]);
                        }
                    }
#pragma unroll
                    for (int nn = 0; nn < 6; ++nn) {
                        const int nt = half * 6 + nn;
                        const u32 cb = (u32)(nt * 8 + 2 * tig) * 4u;
                        sts64(base0 + cb, pack2(acc[nn][0], acc[nn][1]));
                        sts64(base1 + cb, pack2(acc[nn][2], acc[nn][3]));
                    }
                }
            }
            bar_all();
        }
    }
}

extern "C" void kernel_launch(void* const* d_in, const int* in_sizes, int n_in,
                              void* d_out, int out_size) {
    const float* x        = (const float*)d_in[0];
    const float* proj1_w  = (const float*)d_in[1];
    const float* proj1_b  = (const float*)d_in[2];
    const float* gru1_wih = (const float*)d_in[3];
    const float* gru1_whh = (const float*)d_in[4];
    const float* gru1_bih = (const float*)d_in[5];
    const float* gru1_bhh = (const float*)d_in[6];
    const float* proj2_w  = (const float*)d_in[7];
    const float* proj2_b  = (const float*)d_in[8];
    const float* gru2_wih = (const float*)d_in[9];
    const float* gru2_whh = (const float*)d_in[10];
    const float* gru2_bih = (const float*)d_in[11];
    const float* gru2_bhh = (const float*)d_in[12];
    const float* clf_w    = (const float*)d_in[13];
    const float* clf_b    = (const float*)d_in[14];
    float* out = (float*)d_out;

    float *pa, *pc, *ph1;
    cudaGetSymbolAddress((void**)&pa, g_a);
    cudaGetSymbolAddress((void**)&pc, g_c);
    cudaGetSymbolAddress((void**)&ph1, g_h1);

    // Stage 1
    pre_kernel<16><<<128, 256>>>(x, proj1_w, proj1_b, pa, pc);
    gru_fused_kernel<0><<<128, 256>>>(pa, pc, gru1_wih, gru1_whh, gru1_bih,
                                      gru1_bhh, nullptr, nullptr, ph1);
    // Stage 2
    pre_kernel<32><<<128, 256>>>(ph1, proj2_w, proj2_b, pa, pc);
    gru_fused_kernel<1><<<128, 256>>>(pa, pc, gru2_wih, gru2_whh, gru2_bih,
                                      gru2_bhh, clf_w, clf_b, out);
}